// round 14
// baseline (speedup 1.0000x reference)
#include <cuda_runtime.h>
#include <cuda_bf16.h>
#include <cstdint>
#include <math.h>

#define FIELD 39
#define EMBD 8
#define MAXB 16384
#define D0 312
#define D0P 320
#define D1 512
#define D2 256
#define D3 128

#define KW0 (D0P / 2)    // 160
#define KW1 (D1 / 2)     // 256
#define KW2 (D2 / 2)     // 128

// Scratch (allocation-free rule). Activations packed bf16x2, k-contiguous.
__device__ float    g_li[MAXB];
__device__ unsigned g_h0[MAXB * KW0];
__device__ unsigned g_h1[MAXB * KW1];
// packed weights, layout [N][KW]
__device__ unsigned g_w0p[D1 * KW0];
__device__ unsigned g_w1p[D2 * KW1];
__device__ unsigned g_w2p[D3 * KW2];

#define PACK_TOTAL (D1 * KW0 + D2 * KW1 + D3 * KW2)   // 163840

__device__ __forceinline__ unsigned pack_bf2(float a, float b) {
    __nv_bfloat162 p = __floats2bfloat162_rn(a, b);
    return *(unsigned*)&p;
}

// ---------------------------------------------------------------------------
// 1. prep kernel (verbatim R7): gather | linear+inter | weight pack
// ---------------------------------------------------------------------------
__global__ __launch_bounds__(256) void prep_kernel(
    const int* __restrict__ ids, const float* __restrict__ vals,
    const float* __restrict__ FM_W, const float* __restrict__ FM_V,
    const float* __restrict__ FM_B, const float* __restrict__ emb,
    const float* __restrict__ W0, const float* __restrict__ W1,
    const float* __restrict__ W2, int B, int gB, int lB)
{
    const int bid = blockIdx.x;
    const int tid = threadIdx.x;

    if (bid < gB) {
        int idx = bid * 256 + tid;
        if (idx >= B * 40) return;
        int b = idx / 40, f = idx % 40;
        uint4 o;
        if (f < FIELD) {
            int id = ids[b * FIELD + f];
            const float4* e = (const float4*)(emb + (size_t)id * EMBD);
            float4 e0 = e[0];
            float4 e1 = e[1];
            o.x = pack_bf2(e0.x, e0.y);
            o.y = pack_bf2(e0.z, e0.w);
            o.z = pack_bf2(e1.x, e1.y);
            o.w = pack_bf2(e1.z, e1.w);
        } else {
            o = make_uint4(0u, 0u, 0u, 0u);
        }
        *(uint4*)(g_h0 + (size_t)b * KW0 + f * 4) = o;
    } else if (bid < gB + lB) {
        __shared__ float Vi[FIELD][8][EMBD];
        __shared__ float Ss[FIELD * FIELD];
        for (int idx = tid; idx < FIELD * 64; idx += 256) {
            int i = idx / 64, r = idx % 64;
            long long off = (long long)i * (51000LL * 64LL) + r;
            Vi[i][r >> 3][r & 7] = FM_V[off];
        }
        __syncthreads();
        for (int idx = tid; idx < FIELD * FIELD; idx += 256) {
            int i = idx / FIELD, j = idx % FIELD;
            float s = 0.f;
            if (j > i) {
#pragma unroll
                for (int e = 0; e < EMBD; e++)
                    s += Vi[i][j & 7][e] * Vi[j][i & 7][e];
            }
            Ss[idx] = s;
        }
        __syncthreads();

        int b = (bid - gB) * 256 + tid;
        if (b >= B) return;
        float v[FIELD];
        float lin = 0.f;
#pragma unroll
        for (int f = 0; f < FIELD; f++) {
            v[f] = vals[b * FIELD + f];
            lin += FM_W[ids[b * FIELD + f]] * v[f];
        }
        float inter = 0.f;
#pragma unroll
        for (int i = 0; i < FIELD; i++) {
            float ti = 0.f;
#pragma unroll
            for (int j = i + 1; j < FIELD; j++)
                ti += Ss[i * FIELD + j] * v[j];
            inter += v[i] * ti;
        }
        g_li[b] = lin + inter + FM_B[0];
    } else {
        int p = (bid - gB - lB) * 256 + tid;
        if (p >= PACK_TOTAL) return;
        if (p < D1 * KW0) {
            int n = p / KW0, kp = p % KW0;
            int k = 2 * kp;
            float a = (k     < D0) ? W0[(size_t)k * D1 + n]       : 0.f;
            float c = (k + 1 < D0) ? W0[(size_t)(k + 1) * D1 + n] : 0.f;
            g_w0p[p] = pack_bf2(a, c);
        } else if (p < D1 * KW0 + D2 * KW1) {
            int q = p - D1 * KW0;
            int n = q / KW1, kp = q % KW1;
            int k = 2 * kp;
            g_w1p[q] = pack_bf2(W1[(size_t)k * D2 + n], W1[(size_t)(k + 1) * D2 + n]);
        } else {
            int q = p - D1 * KW0 - D2 * KW1;
            int n = q / KW2, kp = q % KW2;
            int k = 2 * kp;
            g_w2p[q] = pack_bf2(W2[(size_t)k * D3 + n], W2[(size_t)(k + 1) * D3 + n]);
        }
    }
}

// ---------------------------------------------------------------------------
// HMMA machinery (verbatim R7 semantics): 3 stages, BM=64, BN=128, BK=32,
// 8 warps, warp tile 32x32, distance-2 prefetch.
// ---------------------------------------------------------------------------
#define SSTG 3
#define ASTG (64 * 16)    // 1024 words per A stage
#define BSTG (128 * 16)   // 2048 words per B stage

__device__ __forceinline__ void ldmx4(unsigned &r0, unsigned &r1, unsigned &r2,
                                      unsigned &r3, unsigned addr) {
    asm volatile("ldmatrix.sync.aligned.m8n8.x4.shared.b16 {%0,%1,%2,%3}, [%4];"
                 : "=r"(r0), "=r"(r1), "=r"(r2), "=r"(r3) : "r"(addr));
}

__device__ __forceinline__ void mma_bf16(float* c, const unsigned* a, const unsigned* b) {
    asm volatile(
        "mma.sync.aligned.m16n8k16.row.col.f32.bf16.bf16.f32 "
        "{%0,%1,%2,%3}, {%4,%5,%6,%7}, {%8,%9}, {%0,%1,%2,%3};"
        : "+f"(c[0]), "+f"(c[1]), "+f"(c[2]), "+f"(c[3])
        : "r"(a[0]), "r"(a[1]), "r"(a[2]), "r"(a[3]), "r"(b[0]), "r"(b[1]));
}

struct Frag { float acc[2][4][4]; };

// one k-tile compute; aOff/bOff are full smem byte addresses of the tile
__device__ __forceinline__ void tile_compute(
    unsigned aOff, unsigned bOff, int lane, int wm, int wn, Frag &F)
{
    const int lrow = lane & 15;
    const int lsel = lane >> 4;
#pragma unroll
    for (int s = 0; s < 2; s++) {
        unsigned a[2][4], b[4][2];
        int lc = 2 * s + lsel;
#pragma unroll
        for (int p = 0; p < 2; p++) {
            int n = wn + p * 16 + lrow;
            int pc = lc ^ ((n >> 1) & 3);
            unsigned r0, r1, r2, r3;
            ldmx4(r0, r1, r2, r3, bOff + (n * 16 + pc * 4) * 4);
            b[2 * p][0] = r0;  b[2 * p + 1][0] = r1;
            b[2 * p][1] = r2;  b[2 * p + 1][1] = r3;
        }
#pragma unroll
        for (int mt = 0; mt < 2; mt++) {
            int m = wm + mt * 16 + lrow;
            int pc = lc ^ ((m >> 1) & 3);
            ldmx4(a[mt][0], a[mt][1], a[mt][2], a[mt][3],
                  aOff + (m * 16 + pc * 4) * 4);
        }
#pragma unroll
        for (int mt = 0; mt < 2; mt++)
#pragma unroll
            for (int nt = 0; nt < 4; nt++)
                mma_bf16(F.acc[mt][nt], a[mt], b[nt]);
    }
}

__device__ __forceinline__ void load_B(
    const unsigned* __restrict__ Wp, int KW, int bn, unsigned bBase,
    int t, int st, int kt)
{
    int kw0 = kt * 16;
#pragma unroll
    for (int i = 0; i < 2; i++) {
        int idx = t + 256 * i;
        int n = idx >> 2, c = idx & 3;
        int pc = c ^ ((n >> 1) & 3);
        const unsigned* g = Wp + (size_t)(bn + n) * KW + kw0 + c * 4;
        unsigned s = bBase + (st * BSTG + n * 16 + pc * 4) * 4;
        asm volatile("cp.async.cg.shared.global [%0], [%1], 16;" :: "r"(s), "l"(g));
    }
}

__device__ __forceinline__ void load_A(
    const unsigned* __restrict__ A, int KW, int bm, unsigned aBase,
    int t, int st, int kt)
{
    int m = t >> 2, c = t & 3;
    int pc = c ^ ((m >> 1) & 3);
    const unsigned* g = A + (size_t)(bm + m) * KW + kt * 16 + c * 4;
    unsigned s = aBase + (st * ASTG + m * 16 + pc * 4) * 4;
    asm volatile("cp.async.cg.shared.global [%0], [%1], 16;" :: "r"(s), "l"(g));
}

// ---------------------------------------------------------------------------
// 2. GEMM0 (verbatim R7 structure): h0 @ W0 -> h1, bias+relu, packed out
// ---------------------------------------------------------------------------
__global__ __launch_bounds__(256, 3) void gemm0(
    const unsigned* __restrict__ A, const unsigned* __restrict__ Wp,
    const float* __restrict__ bias, unsigned* __restrict__ C)
{
    __shared__ unsigned As[SSTG * ASTG];
    __shared__ unsigned Bs[SSTG * BSTG];

    const int t = threadIdx.x;
    const int lane = t & 31;
    const int warp = t >> 5;
    const int wm = (warp >> 2) * 32;
    const int wn = (warp & 3) * 32;
    const int bm = blockIdx.y * 64;
    const int bn = blockIdx.x * 128;
    const unsigned aBase = (unsigned)__cvta_generic_to_shared(As);
    const unsigned bBase = (unsigned)__cvta_generic_to_shared(Bs);
    const int nk = KW0 >> 4;   // 10

    Frag F = {};

    load_A(A, KW0, bm, aBase, t, 0, 0);
    load_B(Wp, KW0, bn, bBase, t, 0, 0);
    asm volatile("cp.async.commit_group;" ::: "memory");
    load_A(A, KW0, bm, aBase, t, 1, 1);
    load_B(Wp, KW0, bn, bBase, t, 1, 1);
    asm volatile("cp.async.commit_group;" ::: "memory");

    for (int kt = 0; kt < nk; kt++) {
        asm volatile("cp.async.wait_group 1;" ::: "memory");
        __syncthreads();

        int pf = kt + 2;
        if (pf < nk) {
            load_A(A, KW0, bm, aBase, t, pf % SSTG, pf);
            load_B(Wp, KW0, bn, bBase, t, pf % SSTG, pf);
        }
        asm volatile("cp.async.commit_group;" ::: "memory");

        tile_compute(aBase + (kt % SSTG) * ASTG * 4,
                     bBase + (kt % SSTG) * BSTG * 4, lane, wm, wn, F);
    }

    const int r = lane >> 2, cc = lane & 3;
    const int NW = D1 >> 1;
#pragma unroll
    for (int nt = 0; nt < 4; nt++) {
        int col = bn + wn + nt * 8 + 2 * cc;
        float b0 = bias[col], b1 = bias[col + 1];
        int cw = col >> 1;
#pragma unroll
        for (int mt = 0; mt < 2; mt++) {
            int row0 = bm + wm + mt * 16 + r;
            unsigned o0 = pack_bf2(fmaxf(F.acc[mt][nt][0] + b0, 0.f),
                                   fmaxf(F.acc[mt][nt][1] + b1, 0.f));
            unsigned o1 = pack_bf2(fmaxf(F.acc[mt][nt][2] + b0, 0.f),
                                   fmaxf(F.acc[mt][nt][3] + b1, 0.f));
            C[(size_t)row0 * NW + cw] = o0;
            C[(size_t)(row0 + 8) * NW + cw] = o1;
        }
    }
}

// ---------------------------------------------------------------------------
// 3. fused GEMM1 + GEMM2 + head. One CTA = 64-sample band.
//    layer1: 2 n-tile passes (nk=16), h2 -> smem in A layout.
//    layer2: nk=8, A from resident smem (no A cp.async), B pipelined.
//    head: relu dot outW, cross-warp reduce, + li, sigmoid.
// smem words: A stages [0,3072) | B stages [3072,9216) | h2 [9216,17408)
//             | red [17408,17664)
// ---------------------------------------------------------------------------
#define F_AW 0
#define F_BW 3072
#define F_H2 9216
#define F_RED 17408
#define FSM ((F_RED + 256) * 4)   // 70656 bytes

__global__ __launch_bounds__(256, 3) void gemm12_head(
    const unsigned* __restrict__ A, const unsigned* __restrict__ Wp1,
    const unsigned* __restrict__ Wp2,
    const float* __restrict__ B1v, const float* __restrict__ B2v,
    const float* __restrict__ outW, const float* __restrict__ outB,
    float* __restrict__ out)
{
    extern __shared__ unsigned sm[];
    const int t = threadIdx.x;
    const int lane = t & 31;
    const int warp = t >> 5;
    const int wm = (warp >> 2) * 32;
    const int wn = (warp & 3) * 32;
    const int bm = blockIdx.x * 64;
    const unsigned base = (unsigned)__cvta_generic_to_shared(sm);
    const unsigned aBase = base + F_AW * 4;
    const unsigned bBase = base + F_BW * 4;
    const unsigned h2Base = base + F_H2 * 4;
    const int r = lane >> 2, cc = lane & 3;

    // ================= layer 1: h1 @ W1 -> h2 (smem) =================
#pragma unroll 1
    for (int nt2 = 0; nt2 < 2; nt2++) {
        const int bn = nt2 * 128;
        Frag F = {};

        load_A(A, KW1, bm, aBase, t, 0, 0);
        load_B(Wp1, KW1, bn, bBase, t, 0, 0);
        asm volatile("cp.async.commit_group;" ::: "memory");
        load_A(A, KW1, bm, aBase, t, 1, 1);
        load_B(Wp1, KW1, bn, bBase, t, 1, 1);
        asm volatile("cp.async.commit_group;" ::: "memory");

        for (int kt = 0; kt < 16; kt++) {
            asm volatile("cp.async.wait_group 1;" ::: "memory");
            __syncthreads();

            int pf = kt + 2;
            if (pf < 16) {
                load_A(A, KW1, bm, aBase, t, pf % SSTG, pf);
                load_B(Wp1, KW1, bn, bBase, t, pf % SSTG, pf);
            }
            asm volatile("cp.async.commit_group;" ::: "memory");

            tile_compute(aBase + (kt % SSTG) * ASTG * 4,
                         bBase + (kt % SSTG) * BSTG * 4, lane, wm, wn, F);
        }
        __syncthreads();   // all tile reads done before h2/stage reuse

        // epilogue -> h2 smem in A layout: kw = col/2, ktile=kw>>4, etc.
#pragma unroll
        for (int nt = 0; nt < 4; nt++) {
            int col = bn + wn + nt * 8 + 2 * cc;
            float b0 = B1v[col], b1 = B1v[col + 1];
            int kw = col >> 1;
            int ktile = kw >> 4, kin = kw & 15, ch = kin >> 2, wi = kin & 3;
#pragma unroll
            for (int h = 0; h < 2; h++) {
                int row = wm + r + 8 * h;
                unsigned v = pack_bf2(fmaxf(F.acc[0][nt][2 * h] + b0, 0.f),
                                      fmaxf(F.acc[0][nt][2 * h + 1] + b1, 0.f));
                int pc2 = ch ^ ((row >> 1) & 3);
                sm[F_H2 + ktile * 1024 + row * 16 + pc2 * 4 + wi] = v;
                row += 16;
                unsigned v2 = pack_bf2(fmaxf(F.acc[1][nt][2 * h] + b0, 0.f),
                                       fmaxf(F.acc[1][nt][2 * h + 1] + b1, 0.f));
                int pc3 = ch ^ ((row >> 1) & 3);
                sm[F_H2 + ktile * 1024 + row * 16 + pc3 * 4 + wi] = v2;
            }
        }
        __syncthreads();
    }

    // ================= layer 2 + head: h2(smem) @ W2 =================
    {
        Frag F = {};
        load_B(Wp2, KW2, 0, bBase, t, 0, 0);
        asm volatile("cp.async.commit_group;" ::: "memory");
        load_B(Wp2, KW2, 0, bBase, t, 1, 1);
        asm volatile("cp.async.commit_group;" ::: "memory");

        for (int kt = 0; kt < 8; kt++) {
            asm volatile("cp.async.wait_group 1;" ::: "memory");
            __syncthreads();

            int pf = kt + 2;
            if (pf < 8) load_B(Wp2, KW2, 0, bBase, t, pf % SSTG, pf);
            asm volatile("cp.async.commit_group;" ::: "memory");

            tile_compute(h2Base + kt * 1024 * 4,
                         bBase + (kt % SSTG) * BSTG * 4, lane, wm, wn, F);
        }

        float* red = (float*)(sm + F_RED);
#pragma unroll
        for (int mt = 0; mt < 2; mt++) {
            float p0 = 0.f, p1 = 0.f;
#pragma unroll
            for (int nt = 0; nt < 4; nt++) {
                int col = wn + nt * 8 + 2 * cc;
                float b0 = B2v[col], b1 = B2v[col + 1];
                float w0 = outW[col], w1 = outW[col + 1];
                p0 += fmaxf(F.acc[mt][nt][0] + b0, 0.f) * w0
                    + fmaxf(F.acc[mt][nt][1] + b1, 0.f) * w1;
                p1 += fmaxf(F.acc[mt][nt][2] + b0, 0.f) * w0
                    + fmaxf(F.acc[mt][nt][3] + b1, 0.f) * w1;
            }
            p0 += __shfl_xor_sync(0xffffffffu, p0, 1);
            p0 += __shfl_xor_sync(0xffffffffu, p0, 2);
            p1 += __shfl_xor_sync(0xffffffffu, p1, 1);
            p1 += __shfl_xor_sync(0xffffffffu, p1, 2);
            if (cc == 0) {
                red[(wm + mt * 16 + r) * 4 + (warp & 3)] = p0;
                red[(wm + mt * 16 + r + 8) * 4 + (warp & 3)] = p1;
            }
        }
        __syncthreads();
        if (t < 64) {
            float s = red[t * 4] + red[t * 4 + 1] + red[t * 4 + 2] + red[t * 4 + 3];
            float x = s + outB[0] + g_li[bm + t];
            out[bm + t] = 1.f / (1.f + expf(-x));
        }
    }
}

// ---------------------------------------------------------------------------
extern "C" void kernel_launch(void* const* d_in, const int* in_sizes, int n_in,
                              void* d_out, int out_size)
{
    const int*   feat_ids  = (const int*)  d_in[0];
    const float* feat_vals = (const float*)d_in[1];
    const float* FM_W      = (const float*)d_in[2];
    const float* FM_V      = (const float*)d_in[3];
    const float* FM_B      = (const float*)d_in[4];
    const float* emb       = (const float*)d_in[5];
    const float* W0        = (const float*)d_in[6];
    const float* B0        = (const float*)d_in[7];
    const float* W1        = (const float*)d_in[8];
    const float* B1        = (const float*)d_in[9];
    const float* W2        = (const float*)d_in[10];
    const float* B2        = (const float*)d_in[11];
    const float* outW      = (const float*)d_in[12];
    const float* outB      = (const float*)d_in[13];
    float* out = (float*)d_out;

    int B = in_sizes[0] / FIELD;
    if (B > MAXB) B = MAXB;

    unsigned *h0, *h1, *w0p, *w1p, *w2p;
    cudaGetSymbolAddress((void**)&h0, g_h0);
    cudaGetSymbolAddress((void**)&h1, g_h1);
    cudaGetSymbolAddress((void**)&w0p, g_w0p);
    cudaGetSymbolAddress((void**)&w1p, g_w1p);
    cudaGetSymbolAddress((void**)&w2p, g_w2p);

    cudaFuncSetAttribute(gemm12_head,
                         cudaFuncAttributeMaxDynamicSharedMemorySize, FSM);

    int gB = (B * 40 + 255) / 256;
    int lB = (B + 255) / 256;
    int pB = (PACK_TOTAL + 255) / 256;

    prep_kernel<<<gB + lB + pB, 256>>>(feat_ids, feat_vals, FM_W, FM_V, FM_B, emb,
                                       W0, W1, W2, B, gB, lB);

    gemm0<<<dim3(D1 / 128, B / 64), 256>>>(h0, w0p, B0, h1);

    gemm12_head<<<B / 64, 256, FSM>>>(h1, w1p, w2p, B1, B2, outW, outB, out);
}

// round 15
// speedup vs baseline: 1.3933x; 1.3933x over previous
#include <cuda_runtime.h>
#include <cuda_bf16.h>
#include <cstdint>
#include <math.h>

#define FIELD 39
#define EMBD 8
#define MAXB 16384
#define D0 312
#define D0P 320
#define D1 512
#define D2 256
#define D3 128

#define KW0 (D0P / 2)    // 160
#define KW1 (D1 / 2)     // 256
#define KW2 (D2 / 2)     // 128

// Scratch (allocation-free rule). Activations packed bf16x2, k-contiguous.
__device__ float    g_li[MAXB];
__device__ unsigned g_h0[MAXB * KW0];
__device__ unsigned g_h1[MAXB * KW1];
__device__ unsigned g_h2[MAXB * KW2];
// packed weights, layout [N][KW]
__device__ unsigned g_w0p[D1 * KW0];
__device__ unsigned g_w1p[D2 * KW1];
__device__ unsigned g_w2p[D3 * KW2];

#define PACK_TOTAL (D1 * KW0 + D2 * KW1 + D3 * KW2)   // 163840

__device__ __forceinline__ unsigned pack_bf2(float a, float b) {
    __nv_bfloat162 p = __floats2bfloat162_rn(a, b);
    return *(unsigned*)&p;
}

// ---------------------------------------------------------------------------
// 1. prep kernel: roles (gather x4-ILP | linear+inter | weight pack)
// ---------------------------------------------------------------------------
__global__ __launch_bounds__(256) void prep_kernel(
    const int* __restrict__ ids, const float* __restrict__ vals,
    const float* __restrict__ FM_W, const float* __restrict__ FM_V,
    const float* __restrict__ FM_B, const float* __restrict__ emb,
    const float* __restrict__ W0, const float* __restrict__ W1,
    const float* __restrict__ W2, int B, int gB, int lB)
{
    const int bid = blockIdx.x;
    const int tid = threadIdx.x;

    if (bid < gB) {
        // ---- gather role: 4 (b,f) pairs per thread, batched for MLP ----
        int idv[4];
        int fv[4], bv[4];
        bool ok[4];
#pragma unroll
        for (int u = 0; u < 4; u++) {
            int idx = bid * 1024 + u * 256 + tid;
            int b = idx / 40, f = idx % 40;
            bv[u] = b; fv[u] = f;
            ok[u] = (idx < B * 40) && (f < FIELD);
            idv[u] = ok[u] ? ids[b * FIELD + f] : 0;
        }
        float4 e0[4], e1[4];
#pragma unroll
        for (int u = 0; u < 4; u++) {
            const float4* e = (const float4*)(emb + (size_t)idv[u] * EMBD);
            e0[u] = e[0];
            e1[u] = e[1];
        }
#pragma unroll
        for (int u = 0; u < 4; u++) {
            int idx = bid * 1024 + u * 256 + tid;
            if (idx >= B * 40) continue;
            uint4 o;
            if (ok[u]) {
                o.x = pack_bf2(e0[u].x, e0[u].y);
                o.y = pack_bf2(e0[u].z, e0[u].w);
                o.z = pack_bf2(e1[u].x, e1[u].y);
                o.w = pack_bf2(e1[u].z, e1[u].w);
            } else {
                o = make_uint4(0u, 0u, 0u, 0u);
            }
            *(uint4*)(g_h0 + (size_t)bv[u] * KW0 + fv[u] * 4) = o;
        }
    } else if (bid < gB + lB) {
        __shared__ float Vi[FIELD][8][EMBD];
        __shared__ float Ss[FIELD * FIELD];
        for (int idx = tid; idx < FIELD * 64; idx += 256) {
            int i = idx / 64, r = idx % 64;
            long long off = (long long)i * (51000LL * 64LL) + r;
            Vi[i][r >> 3][r & 7] = FM_V[off];
        }
        __syncthreads();
        for (int idx = tid; idx < FIELD * FIELD; idx += 256) {
            int i = idx / FIELD, j = idx % FIELD;
            float s = 0.f;
            if (j > i) {
#pragma unroll
                for (int e = 0; e < EMBD; e++)
                    s += Vi[i][j & 7][e] * Vi[j][i & 7][e];
            }
            Ss[idx] = s;
        }
        __syncthreads();

        int b = (bid - gB) * 256 + tid;
        if (b >= B) return;
        float v[FIELD];
        float lin = 0.f;
#pragma unroll
        for (int f = 0; f < FIELD; f++) {
            v[f] = vals[b * FIELD + f];
            lin += FM_W[ids[b * FIELD + f]] * v[f];
        }
        float inter = 0.f;
#pragma unroll
        for (int i = 0; i < FIELD; i++) {
            float ti = 0.f;
#pragma unroll
            for (int j = i + 1; j < FIELD; j++)
                ti += Ss[i * FIELD + j] * v[j];
            inter += v[i] * ti;
        }
        g_li[b] = lin + inter + FM_B[0];
    } else {
        int p = (bid - gB - lB) * 256 + tid;
        if (p >= PACK_TOTAL) return;
        if (p < D1 * KW0) {
            int n = p / KW0, kp = p % KW0;
            int k = 2 * kp;
            float a = (k     < D0) ? W0[(size_t)k * D1 + n]       : 0.f;
            float c = (k + 1 < D0) ? W0[(size_t)(k + 1) * D1 + n] : 0.f;
            g_w0p[p] = pack_bf2(a, c);
        } else if (p < D1 * KW0 + D2 * KW1) {
            int q = p - D1 * KW0;
            int n = q / KW1, kp = q % KW1;
            int k = 2 * kp;
            g_w1p[q] = pack_bf2(W1[(size_t)k * D2 + n], W1[(size_t)(k + 1) * D2 + n]);
        } else {
            int q = p - D1 * KW0 - D2 * KW1;
            int n = q / KW2, kp = q % KW2;
            int k = 2 * kp;
            g_w2p[q] = pack_bf2(W2[(size_t)k * D3 + n], W2[(size_t)(k + 1) * D3 + n]);
        }
    }
}

// ---------------------------------------------------------------------------
// HMMA machinery (verbatim R7): 3 stages, BM=64, BN=128, BK=32, 8 warps,
// warp tile 32x32, distance-2 prefetch, static smem.
// ---------------------------------------------------------------------------
#define SSTG 3
#define ASTG (64 * 16)
#define BSTG (128 * 16)

__device__ __forceinline__ void ldmx4(unsigned &r0, unsigned &r1, unsigned &r2,
                                      unsigned &r3, unsigned addr) {
    asm volatile("ldmatrix.sync.aligned.m8n8.x4.shared.b16 {%0,%1,%2,%3}, [%4];"
                 : "=r"(r0), "=r"(r1), "=r"(r2), "=r"(r3) : "r"(addr));
}

__device__ __forceinline__ void mma_bf16(float* c, const unsigned* a, const unsigned* b) {
    asm volatile(
        "mma.sync.aligned.m16n8k16.row.col.f32.bf16.bf16.f32 "
        "{%0,%1,%2,%3}, {%4,%5,%6,%7}, {%8,%9}, {%0,%1,%2,%3};"
        : "+f"(c[0]), "+f"(c[1]), "+f"(c[2]), "+f"(c[3])
        : "r"(a[0]), "r"(a[1]), "r"(a[2]), "r"(a[3]), "r"(b[0]), "r"(b[1]));
}

struct Frag { float acc[2][4][4]; };

__device__ __forceinline__ void tile_compute(
    unsigned aOff, unsigned bOff, int lane, int wm, int wn, Frag &F)
{
    const int lrow = lane & 15;
    const int lsel = lane >> 4;
#pragma unroll
    for (int s = 0; s < 2; s++) {
        unsigned a[2][4], b[4][2];
        int lc = 2 * s + lsel;
#pragma unroll
        for (int p = 0; p < 2; p++) {
            int n = wn + p * 16 + lrow;
            int pc = lc ^ ((n >> 1) & 3);
            unsigned r0, r1, r2, r3;
            ldmx4(r0, r1, r2, r3, bOff + (n * 16 + pc * 4) * 4);
            b[2 * p][0] = r0;  b[2 * p + 1][0] = r1;
            b[2 * p][1] = r2;  b[2 * p + 1][1] = r3;
        }
#pragma unroll
        for (int mt = 0; mt < 2; mt++) {
            int m = wm + mt * 16 + lrow;
            int pc = lc ^ ((m >> 1) & 3);
            ldmx4(a[mt][0], a[mt][1], a[mt][2], a[mt][3],
                  aOff + (m * 16 + pc * 4) * 4);
        }
#pragma unroll
        for (int mt = 0; mt < 2; mt++)
#pragma unroll
            for (int nt = 0; nt < 4; nt++)
                mma_bf16(F.acc[mt][nt], a[mt], b[nt]);
    }
}

__device__ __forceinline__ void load_B(
    const unsigned* __restrict__ Wp, int KW, int bn, unsigned bBase,
    int t, int st, int kt)
{
    int kw0 = kt * 16;
#pragma unroll
    for (int i = 0; i < 2; i++) {
        int idx = t + 256 * i;
        int n = idx >> 2, c = idx & 3;
        int pc = c ^ ((n >> 1) & 3);
        const unsigned* g = Wp + (size_t)(bn + n) * KW + kw0 + c * 4;
        unsigned s = bBase + (st * BSTG + n * 16 + pc * 4) * 4;
        asm volatile("cp.async.cg.shared.global [%0], [%1], 16;" :: "r"(s), "l"(g));
    }
}

__device__ __forceinline__ void load_A(
    const unsigned* __restrict__ A, int KW, int bm, unsigned aBase,
    int t, int st, int kt)
{
    int m = t >> 2, c = t & 3;
    int pc = c ^ ((m >> 1) & 3);
    const unsigned* g = A + (size_t)(bm + m) * KW + kt * 16 + c * 4;
    unsigned s = aBase + (st * ASTG + m * 16 + pc * 4) * 4;
    asm volatile("cp.async.cg.shared.global [%0], [%1], 16;" :: "r"(s), "l"(g));
}

// ---------------------------------------------------------------------------
// 2. GEMM + bias + ReLU -> packed bf16x2 output (layers 0 & 1)
// ---------------------------------------------------------------------------
__global__ __launch_bounds__(256, 3) void gemm_mid(
    const unsigned* __restrict__ A, const unsigned* __restrict__ Wp,
    const float* __restrict__ bias, unsigned* __restrict__ C,
    int N, int KW)
{
    __shared__ unsigned As[SSTG * ASTG];
    __shared__ unsigned Bs[SSTG * BSTG];

    const int t = threadIdx.x;
    const int lane = t & 31;
    const int warp = t >> 5;
    const int wm = (warp >> 2) * 32;
    const int wn = (warp & 3) * 32;
    const int bm = blockIdx.y * 64;
    const int bn = blockIdx.x * 128;
    const unsigned aBase = (unsigned)__cvta_generic_to_shared(As);
    const unsigned bBase = (unsigned)__cvta_generic_to_shared(Bs);
    const int nk = KW >> 4;

    Frag F = {};

    load_A(A, KW, bm, aBase, t, 0, 0);
    load_B(Wp, KW, bn, bBase, t, 0, 0);
    asm volatile("cp.async.commit_group;" ::: "memory");
    load_A(A, KW, bm, aBase, t, 1, 1);
    load_B(Wp, KW, bn, bBase, t, 1, 1);
    asm volatile("cp.async.commit_group;" ::: "memory");

    for (int kt = 0; kt < nk; kt++) {
        asm volatile("cp.async.wait_group 1;" ::: "memory");
        __syncthreads();

        int pf = kt + 2;
        if (pf < nk) {
            load_A(A, KW, bm, aBase, t, pf % SSTG, pf);
            load_B(Wp, KW, bn, bBase, t, pf % SSTG, pf);
        }
        asm volatile("cp.async.commit_group;" ::: "memory");

        tile_compute(aBase + (kt % SSTG) * ASTG * 4,
                     bBase + (kt % SSTG) * BSTG * 4, lane, wm, wn, F);
    }

    const int r = lane >> 2, cc = lane & 3;
    const int NW = N >> 1;
#pragma unroll
    for (int nt = 0; nt < 4; nt++) {
        int col = bn + wn + nt * 8 + 2 * cc;
        float b0 = bias[col], b1 = bias[col + 1];
        int cw = col >> 1;
#pragma unroll
        for (int mt = 0; mt < 2; mt++) {
            int row0 = bm + wm + mt * 16 + r;
            unsigned o0 = pack_bf2(fmaxf(F.acc[mt][nt][0] + b0, 0.f),
                                   fmaxf(F.acc[mt][nt][1] + b1, 0.f));
            unsigned o1 = pack_bf2(fmaxf(F.acc[mt][nt][2] + b0, 0.f),
                                   fmaxf(F.acc[mt][nt][3] + b1, 0.f));
            C[(size_t)row0 * NW + cw] = o0;
            C[(size_t)(row0 + 8) * NW + cw] = o1;
        }
    }
}

// ---------------------------------------------------------------------------
// 3. last GEMM fused with output head (verbatim R7)
// ---------------------------------------------------------------------------
__global__ __launch_bounds__(256, 3) void gemm_last_head(
    const unsigned* __restrict__ A, const unsigned* __restrict__ Wp,
    const float* __restrict__ bias, const float* __restrict__ outW,
    const float* __restrict__ outB, float* __restrict__ out, int KW)
{
    __shared__ unsigned As[SSTG * ASTG];
    __shared__ unsigned Bs[SSTG * BSTG];
    __shared__ float red[64][4];

    const int t = threadIdx.x;
    const int lane = t & 31;
    const int warp = t >> 5;
    const int wm = (warp >> 2) * 32;
    const int wn = (warp & 3) * 32;
    const int bm = blockIdx.x * 64;
    const unsigned aBase = (unsigned)__cvta_generic_to_shared(As);
    const unsigned bBase = (unsigned)__cvta_generic_to_shared(Bs);
    const int nk = KW >> 4;

    Frag F = {};

    load_A(A, KW, bm, aBase, t, 0, 0);
    load_B(Wp, KW, 0, bBase, t, 0, 0);
    asm volatile("cp.async.commit_group;" ::: "memory");
    load_A(A, KW, bm, aBase, t, 1, 1);
    load_B(Wp, KW, 0, bBase, t, 1, 1);
    asm volatile("cp.async.commit_group;" ::: "memory");

    for (int kt = 0; kt < nk; kt++) {
        asm volatile("cp.async.wait_group 1;" ::: "memory");
        __syncthreads();

        int pf = kt + 2;
        if (pf < nk) {
            load_A(A, KW, bm, aBase, t, pf % SSTG, pf);
            load_B(Wp, KW, 0, bBase, t, pf % SSTG, pf);
        }
        asm volatile("cp.async.commit_group;" ::: "memory");

        tile_compute(aBase + (kt % SSTG) * ASTG * 4,
                     bBase + (kt % SSTG) * BSTG * 4, lane, wm, wn, F);
    }

    const int r = lane >> 2, cc = lane & 3;
#pragma unroll
    for (int mt = 0; mt < 2; mt++) {
        float p0 = 0.f, p1 = 0.f;
#pragma unroll
        for (int nt = 0; nt < 4; nt++) {
            int col = wn + nt * 8 + 2 * cc;
            float b0 = bias[col], b1 = bias[col + 1];
            float w0 = outW[col], w1 = outW[col + 1];
            p0 += fmaxf(F.acc[mt][nt][0] + b0, 0.f) * w0
                + fmaxf(F.acc[mt][nt][1] + b1, 0.f) * w1;
            p1 += fmaxf(F.acc[mt][nt][2] + b0, 0.f) * w0
                + fmaxf(F.acc[mt][nt][3] + b1, 0.f) * w1;
        }
        p0 += __shfl_xor_sync(0xffffffffu, p0, 1);
        p0 += __shfl_xor_sync(0xffffffffu, p0, 2);
        p1 += __shfl_xor_sync(0xffffffffu, p1, 1);
        p1 += __shfl_xor_sync(0xffffffffu, p1, 2);
        if (cc == 0) {
            red[wm + mt * 16 + r][warp & 3] = p0;
            red[wm + mt * 16 + r + 8][warp & 3] = p1;
        }
    }
    __syncthreads();
    if (t < 64) {
        float s = red[t][0] + red[t][1] + red[t][2] + red[t][3];
        float x = s + outB[0] + g_li[bm + t];
        out[bm + t] = 1.f / (1.f + expf(-x));
    }
}

// ---------------------------------------------------------------------------
extern "C" void kernel_launch(void* const* d_in, const int* in_sizes, int n_in,
                              void* d_out, int out_size)
{
    const int*   feat_ids  = (const int*)  d_in[0];
    const float* feat_vals = (const float*)d_in[1];
    const float* FM_W      = (const float*)d_in[2];
    const float* FM_V      = (const float*)d_in[3];
    const float* FM_B      = (const float*)d_in[4];
    const float* emb       = (const float*)d_in[5];
    const float* W0        = (const float*)d_in[6];
    const float* B0        = (const float*)d_in[7];
    const float* W1        = (const float*)d_in[8];
    const float* B1        = (const float*)d_in[9];
    const float* W2        = (const float*)d_in[10];
    const float* B2        = (const float*)d_in[11];
    const float* outW      = (const float*)d_in[12];
    const float* outB      = (const float*)d_in[13];
    float* out = (float*)d_out;

    int B = in_sizes[0] / FIELD;
    if (B > MAXB) B = MAXB;

    unsigned *h0, *h1, *h2, *w0p, *w1p, *w2p;
    cudaGetSymbolAddress((void**)&h0, g_h0);
    cudaGetSymbolAddress((void**)&h1, g_h1);
    cudaGetSymbolAddress((void**)&h2, g_h2);
    cudaGetSymbolAddress((void**)&w0p, g_w0p);
    cudaGetSymbolAddress((void**)&w1p, g_w1p);
    cudaGetSymbolAddress((void**)&w2p, g_w2p);

    int gB = (B * 40 + 1023) / 1024;   // 4 pairs per thread
    int lB = (B + 255) / 256;
    int pB = (PACK_TOTAL + 255) / 256;

    prep_kernel<<<gB + lB + pB, 256>>>(feat_ids, feat_vals, FM_W, FM_V, FM_B, emb,
                                       W0, W1, W2, B, gB, lB);

    gemm_mid<<<dim3(D1 / 128, B / 64), 256>>>(h0, w0p, B0, h1, D1, KW0);
    gemm_mid<<<dim3(D2 / 128, B / 64), 256>>>(h1, w1p, B1, h2, D2, KW1);
    gemm_last_head<<<B / 64, 256>>>(h2, w2p, B2, outW, outB, out, KW2);
}

// round 16
// speedup vs baseline: 1.5076x; 1.0821x over previous
#include <cuda_runtime.h>
#include <cuda_bf16.h>
#include <cstdint>
#include <math.h>

#define FIELD 39
#define EMBD 8
#define MAXB 16384
#define D0 312
#define D0P 320
#define D1 512
#define D2 256
#define D3 128

#define KW0 (D0P / 2)    // 160
#define KW1 (D1 / 2)     // 256
#define KW2 (D2 / 2)     // 128

// Scratch (allocation-free rule). Activations packed bf16x2, k-contiguous.
__device__ float    g_li[MAXB];
__device__ unsigned g_h0[MAXB * KW0];
__device__ unsigned g_h1[MAXB * KW1];
__device__ unsigned g_h2[MAXB * KW2];
// packed weights, layout [N][KW]
__device__ unsigned g_w0p[D1 * KW0];
__device__ unsigned g_w1p[D2 * KW1];
__device__ unsigned g_w2p[D3 * KW2];

#define PACK_TOTAL (D1 * KW0 + D2 * KW1 + D3 * KW2)   // 163840

__device__ __forceinline__ unsigned pack_bf2(float a, float b) {
    __nv_bfloat162 p = __floats2bfloat162_rn(a, b);
    return *(unsigned*)&p;
}

// ---------------------------------------------------------------------------
// 1a. gather kernel (R7 gather role verbatim; low-reg, 8 CTAs/SM)
// ---------------------------------------------------------------------------
__global__ __launch_bounds__(256, 8) void gather_k(
    const int* __restrict__ ids, const float* __restrict__ emb, int B)
{
    int idx = blockIdx.x * 256 + threadIdx.x;
    if (idx >= B * 40) return;
    int b = idx / 40, f = idx % 40;
    uint4 o;
    if (f < FIELD) {
        int id = ids[b * FIELD + f];
        const float4* e = (const float4*)(emb + (size_t)id * EMBD);
        float4 e0 = e[0];
        float4 e1 = e[1];
        o.x = pack_bf2(e0.x, e0.y);
        o.y = pack_bf2(e0.z, e0.w);
        o.z = pack_bf2(e1.x, e1.y);
        o.w = pack_bf2(e1.z, e1.w);
    } else {
        o = make_uint4(0u, 0u, 0u, 0u);
    }
    *(uint4*)(g_h0 + (size_t)b * KW0 + f * 4) = o;
}

// ---------------------------------------------------------------------------
// 1b. li + pack kernel (R7 roles verbatim)
// ---------------------------------------------------------------------------
__global__ __launch_bounds__(256, 4) void lipack_k(
    const int* __restrict__ ids, const float* __restrict__ vals,
    const float* __restrict__ FM_W, const float* __restrict__ FM_V,
    const float* __restrict__ FM_B,
    const float* __restrict__ W0, const float* __restrict__ W1,
    const float* __restrict__ W2, int B, int lB)
{
    const int bid = blockIdx.x;
    const int tid = threadIdx.x;

    if (bid < lB) {
        __shared__ float Vi[FIELD][8][EMBD];
        __shared__ float Ss[FIELD * FIELD];
        for (int idx = tid; idx < FIELD * 64; idx += 256) {
            int i = idx / 64, r = idx % 64;
            long long off = (long long)i * (51000LL * 64LL) + r;
            Vi[i][r >> 3][r & 7] = FM_V[off];
        }
        __syncthreads();
        for (int idx = tid; idx < FIELD * FIELD; idx += 256) {
            int i = idx / FIELD, j = idx % FIELD;
            float s = 0.f;
            if (j > i) {
#pragma unroll
                for (int e = 0; e < EMBD; e++)
                    s += Vi[i][j & 7][e] * Vi[j][i & 7][e];
            }
            Ss[idx] = s;
        }
        __syncthreads();

        int b = bid * 256 + tid;
        if (b >= B) return;
        float v[FIELD];
        float lin = 0.f;
#pragma unroll
        for (int f = 0; f < FIELD; f++) {
            v[f] = vals[b * FIELD + f];
            lin += FM_W[ids[b * FIELD + f]] * v[f];
        }
        float inter = 0.f;
#pragma unroll
        for (int i = 0; i < FIELD; i++) {
            float ti = 0.f;
#pragma unroll
            for (int j = i + 1; j < FIELD; j++)
                ti += Ss[i * FIELD + j] * v[j];
            inter += v[i] * ti;
        }
        g_li[b] = lin + inter + FM_B[0];
    } else {
        int p = (bid - lB) * 256 + tid;
        if (p >= PACK_TOTAL) return;
        if (p < D1 * KW0) {
            int n = p / KW0, kp = p % KW0;
            int k = 2 * kp;
            float a = (k     < D0) ? W0[(size_t)k * D1 + n]       : 0.f;
            float c = (k + 1 < D0) ? W0[(size_t)(k + 1) * D1 + n] : 0.f;
            g_w0p[p] = pack_bf2(a, c);
        } else if (p < D1 * KW0 + D2 * KW1) {
            int q = p - D1 * KW0;
            int n = q / KW1, kp = q % KW1;
            int k = 2 * kp;
            g_w1p[q] = pack_bf2(W1[(size_t)k * D2 + n], W1[(size_t)(k + 1) * D2 + n]);
        } else {
            int q = p - D1 * KW0 - D2 * KW1;
            int n = q / KW2, kp = q % KW2;
            int k = 2 * kp;
            g_w2p[q] = pack_bf2(W2[(size_t)k * D3 + n], W2[(size_t)(k + 1) * D3 + n]);
        }
    }
}

// ---------------------------------------------------------------------------
// HMMA machinery (verbatim R7): 3 stages, BM=64, BN=128, BK=32, 8 warps,
// warp tile 32x32, distance-2 prefetch, static smem.
// ---------------------------------------------------------------------------
#define SSTG 3
#define ASTG (64 * 16)
#define BSTG (128 * 16)

__device__ __forceinline__ void ldmx4(unsigned &r0, unsigned &r1, unsigned &r2,
                                      unsigned &r3, unsigned addr) {
    asm volatile("ldmatrix.sync.aligned.m8n8.x4.shared.b16 {%0,%1,%2,%3}, [%4];"
                 : "=r"(r0), "=r"(r1), "=r"(r2), "=r"(r3) : "r"(addr));
}

__device__ __forceinline__ void mma_bf16(float* c, const unsigned* a, const unsigned* b) {
    asm volatile(
        "mma.sync.aligned.m16n8k16.row.col.f32.bf16.bf16.f32 "
        "{%0,%1,%2,%3}, {%4,%5,%6,%7}, {%8,%9}, {%0,%1,%2,%3};"
        : "+f"(c[0]), "+f"(c[1]), "+f"(c[2]), "+f"(c[3])
        : "r"(a[0]), "r"(a[1]), "r"(a[2]), "r"(a[3]), "r"(b[0]), "r"(b[1]));
}

struct Frag { float acc[2][4][4]; };

__device__ __forceinline__ void tile_compute(
    unsigned aOff, unsigned bOff, int lane, int wm, int wn, Frag &F)
{
    const int lrow = lane & 15;
    const int lsel = lane >> 4;
#pragma unroll
    for (int s = 0; s < 2; s++) {
        unsigned a[2][4], b[4][2];
        int lc = 2 * s + lsel;
#pragma unroll
        for (int p = 0; p < 2; p++) {
            int n = wn + p * 16 + lrow;
            int pc = lc ^ ((n >> 1) & 3);
            unsigned r0, r1, r2, r3;
            ldmx4(r0, r1, r2, r3, bOff + (n * 16 + pc * 4) * 4);
            b[2 * p][0] = r0;  b[2 * p + 1][0] = r1;
            b[2 * p][1] = r2;  b[2 * p + 1][1] = r3;
        }
#pragma unroll
        for (int mt = 0; mt < 2; mt++) {
            int m = wm + mt * 16 + lrow;
            int pc = lc ^ ((m >> 1) & 3);
            ldmx4(a[mt][0], a[mt][1], a[mt][2], a[mt][3],
                  aOff + (m * 16 + pc * 4) * 4);
        }
#pragma unroll
        for (int mt = 0; mt < 2; mt++)
#pragma unroll
            for (int nt = 0; nt < 4; nt++)
                mma_bf16(F.acc[mt][nt], a[mt], b[nt]);
    }
}

__device__ __forceinline__ void load_B(
    const unsigned* __restrict__ Wp, int KW, int bn, unsigned bBase,
    int t, int st, int kt)
{
    int kw0 = kt * 16;
#pragma unroll
    for (int i = 0; i < 2; i++) {
        int idx = t + 256 * i;
        int n = idx >> 2, c = idx & 3;
        int pc = c ^ ((n >> 1) & 3);
        const unsigned* g = Wp + (size_t)(bn + n) * KW + kw0 + c * 4;
        unsigned s = bBase + (st * BSTG + n * 16 + pc * 4) * 4;
        asm volatile("cp.async.cg.shared.global [%0], [%1], 16;" :: "r"(s), "l"(g));
    }
}

__device__ __forceinline__ void load_A(
    const unsigned* __restrict__ A, int KW, int bm, unsigned aBase,
    int t, int st, int kt)
{
    int m = t >> 2, c = t & 3;
    int pc = c ^ ((m >> 1) & 3);
    const unsigned* g = A + (size_t)(bm + m) * KW + kt * 16 + c * 4;
    unsigned s = aBase + (st * ASTG + m * 16 + pc * 4) * 4;
    asm volatile("cp.async.cg.shared.global [%0], [%1], 16;" :: "r"(s), "l"(g));
}

// ---------------------------------------------------------------------------
// 2. GEMM + bias + ReLU -> packed bf16x2 output (layers 0 & 1) [verbatim R7]
// ---------------------------------------------------------------------------
__global__ __launch_bounds__(256, 3) void gemm_mid(
    const unsigned* __restrict__ A, const unsigned* __restrict__ Wp,
    const float* __restrict__ bias, unsigned* __restrict__ C,
    int N, int KW)
{
    __shared__ unsigned As[SSTG * ASTG];
    __shared__ unsigned Bs[SSTG * BSTG];

    const int t = threadIdx.x;
    const int lane = t & 31;
    const int warp = t >> 5;
    const int wm = (warp >> 2) * 32;
    const int wn = (warp & 3) * 32;
    const int bm = blockIdx.y * 64;
    const int bn = blockIdx.x * 128;
    const unsigned aBase = (unsigned)__cvta_generic_to_shared(As);
    const unsigned bBase = (unsigned)__cvta_generic_to_shared(Bs);
    const int nk = KW >> 4;

    Frag F = {};

    load_A(A, KW, bm, aBase, t, 0, 0);
    load_B(Wp, KW, bn, bBase, t, 0, 0);
    asm volatile("cp.async.commit_group;" ::: "memory");
    load_A(A, KW, bm, aBase, t, 1, 1);
    load_B(Wp, KW, bn, bBase, t, 1, 1);
    asm volatile("cp.async.commit_group;" ::: "memory");

    for (int kt = 0; kt < nk; kt++) {
        asm volatile("cp.async.wait_group 1;" ::: "memory");
        __syncthreads();

        int pf = kt + 2;
        if (pf < nk) {
            load_A(A, KW, bm, aBase, t, pf % SSTG, pf);
            load_B(Wp, KW, bn, bBase, t, pf % SSTG, pf);
        }
        asm volatile("cp.async.commit_group;" ::: "memory");

        tile_compute(aBase + (kt % SSTG) * ASTG * 4,
                     bBase + (kt % SSTG) * BSTG * 4, lane, wm, wn, F);
    }

    const int r = lane >> 2, cc = lane & 3;
    const int NW = N >> 1;
#pragma unroll
    for (int nt = 0; nt < 4; nt++) {
        int col = bn + wn + nt * 8 + 2 * cc;
        float b0 = bias[col], b1 = bias[col + 1];
        int cw = col >> 1;
#pragma unroll
        for (int mt = 0; mt < 2; mt++) {
            int row0 = bm + wm + mt * 16 + r;
            unsigned o0 = pack_bf2(fmaxf(F.acc[mt][nt][0] + b0, 0.f),
                                   fmaxf(F.acc[mt][nt][1] + b1, 0.f));
            unsigned o1 = pack_bf2(fmaxf(F.acc[mt][nt][2] + b0, 0.f),
                                   fmaxf(F.acc[mt][nt][3] + b1, 0.f));
            C[(size_t)row0 * NW + cw] = o0;
            C[(size_t)(row0 + 8) * NW + cw] = o1;
        }
    }
}

// ---------------------------------------------------------------------------
// 3. last GEMM fused with output head (verbatim R7)
// ---------------------------------------------------------------------------
__global__ __launch_bounds__(256, 3) void gemm_last_head(
    const unsigned* __restrict__ A, const unsigned* __restrict__ Wp,
    const float* __restrict__ bias, const float* __restrict__ outW,
    const float* __restrict__ outB, float* __restrict__ out, int KW)
{
    __shared__ unsigned As[SSTG * ASTG];
    __shared__ unsigned Bs[SSTG * BSTG];
    __shared__ float red[64][4];

    const int t = threadIdx.x;
    const int lane = t & 31;
    const int warp = t >> 5;
    const int wm = (warp >> 2) * 32;
    const int wn = (warp & 3) * 32;
    const int bm = blockIdx.x * 64;
    const unsigned aBase = (unsigned)__cvta_generic_to_shared(As);
    const unsigned bBase = (unsigned)__cvta_generic_to_shared(Bs);
    const int nk = KW >> 4;

    Frag F = {};

    load_A(A, KW, bm, aBase, t, 0, 0);
    load_B(Wp, KW, 0, bBase, t, 0, 0);
    asm volatile("cp.async.commit_group;" ::: "memory");
    load_A(A, KW, bm, aBase, t, 1, 1);
    load_B(Wp, KW, 0, bBase, t, 1, 1);
    asm volatile("cp.async.commit_group;" ::: "memory");

    for (int kt = 0; kt < nk; kt++) {
        asm volatile("cp.async.wait_group 1;" ::: "memory");
        __syncthreads();

        int pf = kt + 2;
        if (pf < nk) {
            load_A(A, KW, bm, aBase, t, pf % SSTG, pf);
            load_B(Wp, KW, 0, bBase, t, pf % SSTG, pf);
        }
        asm volatile("cp.async.commit_group;" ::: "memory");

        tile_compute(aBase + (kt % SSTG) * ASTG * 4,
                     bBase + (kt % SSTG) * BSTG * 4, lane, wm, wn, F);
    }

    const int r = lane >> 2, cc = lane & 3;
#pragma unroll
    for (int mt = 0; mt < 2; mt++) {
        float p0 = 0.f, p1 = 0.f;
#pragma unroll
        for (int nt = 0; nt < 4; nt++) {
            int col = wn + nt * 8 + 2 * cc;
            float b0 = bias[col], b1 = bias[col + 1];
            float w0 = outW[col], w1 = outW[col + 1];
            p0 += fmaxf(F.acc[mt][nt][0] + b0, 0.f) * w0
                + fmaxf(F.acc[mt][nt][1] + b1, 0.f) * w1;
            p1 += fmaxf(F.acc[mt][nt][2] + b0, 0.f) * w0
                + fmaxf(F.acc[mt][nt][3] + b1, 0.f) * w1;
        }
        p0 += __shfl_xor_sync(0xffffffffu, p0, 1);
        p0 += __shfl_xor_sync(0xffffffffu, p0, 2);
        p1 += __shfl_xor_sync(0xffffffffu, p1, 1);
        p1 += __shfl_xor_sync(0xffffffffu, p1, 2);
        if (cc == 0) {
            red[wm + mt * 16 + r][warp & 3] = p0;
            red[wm + mt * 16 + r + 8][warp & 3] = p1;
        }
    }
    __syncthreads();
    if (t < 64) {
        float s = red[t][0] + red[t][1] + red[t][2] + red[t][3];
        float x = s + outB[0] + g_li[bm + t];
        out[bm + t] = 1.f / (1.f + expf(-x));
    }
}

// ---------------------------------------------------------------------------
extern "C" void kernel_launch(void* const* d_in, const int* in_sizes, int n_in,
                              void* d_out, int out_size)
{
    const int*   feat_ids  = (const int*)  d_in[0];
    const float* feat_vals = (const float*)d_in[1];
    const float* FM_W      = (const float*)d_in[2];
    const float* FM_V      = (const float*)d_in[3];
    const float* FM_B      = (const float*)d_in[4];
    const float* emb       = (const float*)d_in[5];
    const float* W0        = (const float*)d_in[6];
    const float* B0        = (const float*)d_in[7];
    const float* W1        = (const float*)d_in[8];
    const float* B1        = (const float*)d_in[9];
    const float* W2        = (const float*)d_in[10];
    const float* B2        = (const float*)d_in[11];
    const float* outW      = (const float*)d_in[12];
    const float* outB      = (const float*)d_in[13];
    float* out = (float*)d_out;

    int B = in_sizes[0] / FIELD;
    if (B > MAXB) B = MAXB;

    unsigned *h0, *h1, *h2, *w0p, *w1p, *w2p;
    cudaGetSymbolAddress((void**)&h0, g_h0);
    cudaGetSymbolAddress((void**)&h1, g_h1);
    cudaGetSymbolAddress((void**)&h2, g_h2);
    cudaGetSymbolAddress((void**)&w0p, g_w0p);
    cudaGetSymbolAddress((void**)&w1p, g_w1p);
    cudaGetSymbolAddress((void**)&w2p, g_w2p);

    int gB = (B * 40 + 255) / 256;
    int lB = (B + 255) / 256;
    int pB = (PACK_TOTAL + 255) / 256;

    gather_k<<<gB, 256>>>(feat_ids, emb, B);
    lipack_k<<<lB + pB, 256>>>(feat_ids, feat_vals, FM_W, FM_V, FM_B,
                               W0, W1, W2, B, lB);

    gemm_mid<<<dim3(D1 / 128, B / 64), 256>>>(h0, w0p, B0, h1, D1, KW0);
    gemm_mid<<<dim3(D2 / 128, B / 64), 256>>>(h1, w1p, B1, h2, D2, KW1);
    gemm_last_head<<<B / 64, 256>>>(h2, w2p, B2, outW, outB, out, KW2);
}